// round 12
// baseline (speedup 1.0000x reference)
#include <cuda_runtime.h>
#include <cuda_fp16.h>
#include <cstdint>

// ---------------------------------------------------------------------------
// HierarchUpdateMlp — fp16 mma.sync (m16n8k16).
//   L1: R7-exact M128N128 pipeline (fp32 staging + convert).
//   L2/L3: 64x128 tile, two 128-thread warp-groups ping-pong over K stages,
//          each with private cp.async pipeline + named barrier; partial-sum
//          exchange at the end. De-lock-steps the SM.
// fp16 smem tiles: rows x 64 halfs (128B rows), chunk pos = j ^ (row&7).
// ---------------------------------------------------------------------------

#define NROWS_MAX 50176   // N = 50000

__device__ __align__(16) __half g_W1_0h[128 * 1280];
__device__ __align__(16) __half g_W1h[6 * 128 * 512];
__device__ __align__(16) __half g_W2h[6 * 128 * 256];
__device__ __align__(16) __half g_Wfh[256 * 768];
__device__ __align__(16) __half g_out1h[(size_t)NROWS_MAX * 896];
__device__ __align__(16) __half g_out2h[(size_t)NROWS_MAX * 768];

__constant__ int c_jA[7] = {0, 5, 7, 8, 11, 13, 14};
__constant__ int c_jB[7] = {0, 6, 9, 10, 12, 15, 16};
__constant__ int c_pA[6] = {0, 1, 1, 1, 4, 4};
__constant__ int c_pB[6] = {1, 2, 3, 4, 5, 6};

#define SMEM_L1 81920     // [0,32K) stg, [32K,48K) hA, [48K,80K) hB x2
#define SMEM_PP 98304     // [0,32K) hA 4x8KB bufs, [32K,96K) hB 4x16KB bufs

__device__ __forceinline__ unsigned smem_u32(const void* p) {
    return (unsigned)__cvta_generic_to_shared(p);
}

__device__ __forceinline__ void ldsm4(unsigned addr, unsigned& r0, unsigned& r1,
                                      unsigned& r2, unsigned& r3) {
    asm volatile("ldmatrix.sync.aligned.m8n8.x4.shared.b16 {%0,%1,%2,%3}, [%4];"
                 : "=r"(r0), "=r"(r1), "=r"(r2), "=r"(r3)
                 : "r"(addr));
}

__device__ __forceinline__ void mma_f16(float* c, const unsigned* a, const unsigned* b) {
    asm volatile(
        "mma.sync.aligned.m16n8k16.row.col.f32.f16.f16.f32 "
        "{%0,%1,%2,%3}, {%4,%5,%6,%7}, {%8,%9}, {%0,%1,%2,%3};"
        : "+f"(c[0]), "+f"(c[1]), "+f"(c[2]), "+f"(c[3])
        : "r"(a[0]), "r"(a[1]), "r"(a[2]), "r"(a[3]), "r"(b[0]), "r"(b[1]));
}

__device__ __forceinline__ void bar_g(int id) {
    asm volatile("bar.sync %0, %1;" ::"r"(id), "r"(128) : "memory");
}

// ======================= L2/L3: ping-pong 64x128 GEMM =======================
// Block tile M=64, N=128. Warps 0-3 = group0 (even K stages), 4-7 = group1.
// Within a group: warpM = wl&1 (m32), warpN = wl>>1 (n64); warp tile m32n64.
template <bool HALF_OUT, int K>
__device__ __forceinline__ void gemm_pp(
    const __half* __restrict__ A, int lda, int offA0, int offA1, int blk,
    const __half* __restrict__ B, int ldb,
    const float* __restrict__ bias,
    void* __restrict__ Cv, int ldc,
    int nrows)
{
    extern __shared__ char smc[];
    __half* hA = reinterpret_cast<__half*>(smc);            // 4 bufs x 4096 halfs
    __half* hB = reinterpret_cast<__half*>(smc + 32768);    // 4 bufs x 8192 halfs

    const int tid   = threadIdx.x;
    const int lane  = tid & 31;
    const int wid   = tid >> 5;
    const int g     = wid >> 2;          // warp-group 0/1
    const int ltid  = tid & 127;
    const int wl    = wid & 3;
    const int warpM = wl & 1;            // 2 warps over M (32 rows)
    const int warpN = wl >> 1;           // 2 warps over N (64 cols)
    const int tile  = blockIdx.x * 64;
    constexpr int KT  = K >> 6;          // 64-K stages (even for all layers)
    constexpr int KTg = KT >> 1;         // stages per group

    float acc[2][8][4];
#pragma unroll
    for (int i = 0; i < 2; i++)
#pragma unroll
        for (int j = 0; j < 8; j++)
#pragma unroll
            for (int q = 0; q < 4; q++) acc[i][j][q] = 0.f;

    const int rowIn = (lane & 7) + ((lane >> 3) & 1) * 8;
    const int hi    = (lane >> 4) & 1;

    // fill geometry: r-base = ltid>>3 (stride 16 rows per i), j = ltid&7.
    // 16-row stride keeps (r&7) constant -> swizzled dst advances by 2048B.
    const int fr = ltid >> 3;
    const int fj = ltid & 7;

    const __half* aSrc[4];
#pragma unroll
    for (int i = 0; i < 4; ++i) {
        int row = tile + fr + i * 16;
        if (row >= nrows) row = nrows - 1;
        aSrc[i] = A + (long)row * lda;
    }
    const unsigned aDst0 = smem_u32(hA + fr * 64 + 8 * (fj ^ (fr & 7)));
    const __half* bSrc0 = B + (long)fr * ldb + fj * 8;
    const unsigned bDst0 = smem_u32(hB + fr * 64 + 8 * (fj ^ (fr & 7)));

    // bi = buffer index 0..3 (g*2 + parity)
    auto fillA = [&](int kt, int bi) {
        const unsigned off = (unsigned)(bi * 8192) + aDst0;   // 4096 halfs/buf
        int k   = (kt << 6) + fj * 8;
        int col = (k < blk) ? (offA0 + k) : (offA1 + (k - blk));
#pragma unroll
        for (int i = 0; i < 4; ++i)
            asm volatile("cp.async.cg.shared.global [%0], [%1], 16;"
                         ::"r"(off + i * 2048u), "l"(aSrc[i] + col));
    };
    auto fillB = [&](int kt, int bi) {
        const unsigned off = (unsigned)(bi * 16384) + bDst0;  // 8192 halfs/buf
        const __half* src = bSrc0 + (kt << 6);
#pragma unroll
        for (int i = 0; i < 8; ++i)
            asm volatile("cp.async.cg.shared.global [%0], [%1], 16;"
                         ::"r"(off + i * 2048u), "l"(src + (long)i * 16 * ldb));
    };

    auto compute_stage = [&](int bi) {
        const __half* As = hA + bi * 4096;
        const __half* Bs = hB + bi * 8192;
#pragma unroll
        for (int s = 0; s < 4; ++s) {
            const int j = 2 * s + hi;
            unsigned a[2][4];
#pragma unroll
            for (int mf = 0; mf < 2; ++mf) {
                int row = warpM * 32 + mf * 16 + rowIn;      // 0..63
                ldsm4(smem_u32(As + row * 64 + 8 * (j ^ (row & 7))),
                      a[mf][0], a[mf][1], a[mf][2], a[mf][3]);
            }
            unsigned b[8][2];
#pragma unroll
            for (int nq = 0; nq < 4; ++nq) {
                int nrow = warpN * 64 + nq * 16 + rowIn;     // 0..127
                unsigned r0, r1, r2, r3;
                ldsm4(smem_u32(Bs + nrow * 64 + 8 * (j ^ (nrow & 7))),
                      r0, r1, r2, r3);
                b[nq * 2][0]     = r0;
                b[nq * 2 + 1][0] = r1;
                b[nq * 2][1]     = r2;
                b[nq * 2 + 1][1] = r3;
            }
#pragma unroll
            for (int mf = 0; mf < 2; ++mf)
#pragma unroll
                for (int nf = 0; nf < 8; ++nf)
                    mma_f16(acc[mf][nf], a[mf], b[nf]);
        }
    };

    // --- group-private mainloop: group g handles kt = g + 2*i ---
    fillA(g, g * 2); fillB(g, g * 2);
    asm volatile("cp.async.commit_group;");
    if (KTg > 1) {
        fillA(g + 2, g * 2 + 1); fillB(g + 2, g * 2 + 1);
        asm volatile("cp.async.commit_group;");
    }
#pragma unroll 2
    for (int i = 0; i < KTg; ++i) {
        if (i + 1 < KTg) {
            asm volatile("cp.async.wait_group 1;" ::: "memory");  // stage i landed
        } else {
            asm volatile("cp.async.wait_group 0;" ::: "memory");
        }
        bar_g(2 + g);                       // fills visible to group's warps
        compute_stage(g * 2 + (i & 1));
        bar_g(2 + g);                       // group done with this buffer
        if (i + 2 < KTg) {
            int kt = g + 2 * (i + 2);
            fillA(kt, g * 2 + (i & 1)); fillB(kt, g * 2 + (i & 1));
            asm volatile("cp.async.commit_group;");
        }
    }

    // --- partial-sum exchange: group1 -> smem, group0 adds + epilogue ---
    __syncthreads();
    float* exch = reinterpret_cast<float*>(smc);    // 32KB exactly
    float* af   = &acc[0][0][0];
    if (g == 1) {
#pragma unroll
        for (int q = 0; q < 16; ++q)
            *reinterpret_cast<float4*>(exch + (q * 128 + ltid) * 4) =
                reinterpret_cast<float4*>(af)[q];
    }
    __syncthreads();
    if (g == 0) {
#pragma unroll
        for (int q = 0; q < 16; ++q) {
            float4 v = *reinterpret_cast<float4*>(exch + (q * 128 + ltid) * 4);
            af[q * 4 + 0] += v.x; af[q * 4 + 1] += v.y;
            af[q * 4 + 2] += v.z; af[q * 4 + 3] += v.w;
        }
        const int rbase = tile + warpM * 32 + (lane >> 2);
#pragma unroll
        for (int mf = 0; mf < 2; ++mf) {
            int r0 = rbase + mf * 16;
#pragma unroll
            for (int nf = 0; nf < 8; ++nf) {
                int col  = warpN * 64 + nf * 8 + (lane & 3) * 2;
                float b0 = __ldg(bias + col);
                float b1 = __ldg(bias + col + 1);
                float v0 = fmaxf(acc[mf][nf][0] + b0, 0.f);
                float v1 = fmaxf(acc[mf][nf][1] + b1, 0.f);
                float v2 = fmaxf(acc[mf][nf][2] + b0, 0.f);
                float v3 = fmaxf(acc[mf][nf][3] + b1, 0.f);
                if (HALF_OUT) {
                    __half* Ch = (__half*)Cv;
                    if (r0 < nrows)
                        *reinterpret_cast<__half2*>(Ch + (long)r0 * ldc + col) =
                            __floats2half2_rn(v0, v1);
                    if (r0 + 8 < nrows)
                        *reinterpret_cast<__half2*>(Ch + (long)(r0 + 8) * ldc + col) =
                            __floats2half2_rn(v2, v3);
                } else {
                    float* Cf = (float*)Cv;
                    if (r0 < nrows)
                        *reinterpret_cast<float2*>(Cf + (long)r0 * ldc + col) =
                            make_float2(v0, v1);
                    if (r0 + 8 < nrows)
                        *reinterpret_cast<float2*>(Cf + (long)(r0 + 8) * ldc + col) =
                            make_float2(v2, v3);
                }
            }
        }
    }
}

// ======================= L1: R7-exact M128N128 GEMM =========================
template <int K>
__device__ __forceinline__ void gemm_l1(
    const float* __restrict__ Av, int lda, int offA0, int offA1, int blk,
    const __half* __restrict__ B, int ldb,
    const float* __restrict__ bias,
    __half* __restrict__ Cv, int ldc,
    int nrows)
{
    extern __shared__ char smc[];
    float*  stg = reinterpret_cast<float*>(smc);
    __half* hA  = reinterpret_cast<__half*>(smc + 32768);
    __half* hB  = hA + 8192;

    const int tid   = threadIdx.x;
    const int lane  = tid & 31;
    const int wid   = tid >> 5;
    const int warpM = wid & 3;
    const int warpN = wid >> 2;
    const int tile  = blockIdx.x * 128;
    constexpr int KT = K >> 6;

    float acc[2][8][4];
#pragma unroll
    for (int i = 0; i < 2; i++)
#pragma unroll
        for (int j = 0; j < 8; j++)
#pragma unroll
            for (int q = 0; q < 4; q++) acc[i][j][q] = 0.f;

    const int rowIn = (lane & 7) + ((lane >> 3) & 1) * 8;
    const int hi    = (lane >> 4) & 1;

    const int fr8  = tid >> 3;
    const int fj   = tid & 7;
    const int fr16 = tid >> 4;
    const int fj16 = tid & 15;

    const __half* bSrc0 = B + (long)fr8 * ldb + fj * 8;
    unsigned bDst[4];
#pragma unroll
    for (int i = 0; i < 4; ++i) {
        int r = fr8 + i * 32;
        bDst[i] = smem_u32(hB + r * 64 + 8 * (fj ^ (r & 7)));
    }
    auto fillB = [&](int kt) {
        const unsigned boff = (unsigned)((kt & 1) * 16384);
        const __half* src = bSrc0 + (kt << 6);
#pragma unroll
        for (int i = 0; i < 4; ++i)
            asm volatile("cp.async.cg.shared.global [%0], [%1], 16;"
                         ::"r"(bDst[i] + boff), "l"(src + (long)i * 32 * ldb));
    };

    const float* a1Src[8];
    unsigned a1Dst[8];
#pragma unroll
    for (int i = 0; i < 8; ++i) {
        int r = fr16 + i * 16;
        int row = tile + r; if (row >= nrows) row = nrows - 1;
        a1Src[i] = Av + (long)row * lda;
        a1Dst[i] = smem_u32(stg + r * 64 +
                            4 * ((fj16 & 8) | ((fj16 & 7) ^ (r & 7))));
    }
    auto fillA1 = [&](int kt) {
        int k   = (kt << 6) + fj16 * 4;
        int col = (k < blk) ? (offA0 + k) : (offA1 + (k - blk));
#pragma unroll
        for (int i = 0; i < 8; ++i)
            asm volatile("cp.async.cg.shared.global [%0], [%1], 16;"
                         ::"r"(a1Dst[i]), "l"(a1Src[i] + col));
    };

    auto convertA = [&]() {
        const int r  = tid >> 1;
        const int h  = tid & 1;
        const int rx = r & 7;
#pragma unroll
        for (int q = 0; q < 4; ++q) {
            float4 va = *reinterpret_cast<const float4*>(
                stg + r * 64 + 4 * (h * 8 + ((2 * q) ^ rx)));
            float4 vb = *reinterpret_cast<const float4*>(
                stg + r * 64 + 4 * (h * 8 + ((2 * q + 1) ^ rx)));
            __half2 h0 = __floats2half2_rn(va.x, va.y);
            __half2 h1 = __floats2half2_rn(va.z, va.w);
            __half2 h2 = __floats2half2_rn(vb.x, vb.y);
            __half2 h3 = __floats2half2_rn(vb.z, vb.w);
            uint4 u;
            u.x = *reinterpret_cast<unsigned*>(&h0);
            u.y = *reinterpret_cast<unsigned*>(&h1);
            u.z = *reinterpret_cast<unsigned*>(&h2);
            u.w = *reinterpret_cast<unsigned*>(&h3);
            *reinterpret_cast<uint4*>(hA + r * 64 + 8 * ((h * 4 + q) ^ rx)) = u;
        }
    };

    auto compute_stage = [&](int buf) {
        const __half* As = hA;
        const __half* Bs = hB + buf * 8192;
#pragma unroll
        for (int s = 0; s < 4; ++s) {
            const int j = 2 * s + hi;
            unsigned a[2][4];
#pragma unroll
            for (int mf = 0; mf < 2; ++mf) {
                int row = warpM * 32 + mf * 16 + rowIn;
                ldsm4(smem_u32(As + row * 64 + 8 * (j ^ (row & 7))),
                      a[mf][0], a[mf][1], a[mf][2], a[mf][3]);
            }
            unsigned b[8][2];
#pragma unroll
            for (int nq = 0; nq < 4; ++nq) {
                int nrow = warpN * 64 + nq * 16 + rowIn;
                unsigned r0, r1, r2, r3;
                ldsm4(smem_u32(Bs + nrow * 64 + 8 * (j ^ (nrow & 7))),
                      r0, r1, r2, r3);
                b[nq * 2][0]     = r0;
                b[nq * 2 + 1][0] = r1;
                b[nq * 2][1]     = r2;
                b[nq * 2 + 1][1] = r3;
            }
#pragma unroll
            for (int mf = 0; mf < 2; ++mf)
#pragma unroll
                for (int nf = 0; nf < 8; ++nf)
                    mma_f16(acc[mf][nf], a[mf], b[nf]);
        }
    };

    fillA1(0); fillB(0);
    asm volatile("cp.async.commit_group;");
#pragma unroll 4
    for (int kt = 0; kt < KT; ++kt) {
        asm volatile("cp.async.wait_group 0;" ::: "memory");
        __syncthreads();
        convertA();
        __syncthreads();
        if (kt + 1 < KT) {
            fillA1(kt + 1); fillB(kt + 1);
            asm volatile("cp.async.commit_group;");
        }
        compute_stage(kt & 1);
    }

    const int rbase = tile + warpM * 32 + (lane >> 2);
#pragma unroll
    for (int mf = 0; mf < 2; ++mf) {
        int r0 = rbase + mf * 16;
#pragma unroll
        for (int nf = 0; nf < 8; ++nf) {
            int col  = warpN * 64 + nf * 8 + (lane & 3) * 2;
            float b0 = __ldg(bias + col);
            float b1 = __ldg(bias + col + 1);
            float v0 = fmaxf(acc[mf][nf][0] + b0, 0.f);
            float v1 = fmaxf(acc[mf][nf][1] + b1, 0.f);
            float v2 = fmaxf(acc[mf][nf][2] + b0, 0.f);
            float v3 = fmaxf(acc[mf][nf][3] + b1, 0.f);
            if (r0 < nrows)
                *reinterpret_cast<__half2*>(Cv + (long)r0 * ldc + col) =
                    __floats2half2_rn(v0, v1);
            if (r0 + 8 < nrows)
                *reinterpret_cast<__half2*>(Cv + (long)(r0 + 8) * ldc + col) =
                    __floats2half2_rn(v2, v3);
        }
    }
}

// ---------------- kernels ----------------

__global__ void prep_kernel(const float* __restrict__ w10, const float* __restrict__ w1,
                            const float* __restrict__ w2, const float* __restrict__ wf) {
    int i      = blockIdx.x * blockDim.x + threadIdx.x;
    int stride = gridDim.x * blockDim.x;
    for (int j = i; j < 128 * 1280; j += stride) g_W1_0h[j] = __float2half_rn(w10[j]);
    for (int j = i; j < 6 * 128 * 512; j += stride) g_W1h[j] = __float2half_rn(w1[j]);
    for (int j = i; j < 6 * 128 * 256; j += stride) g_W2h[j] = __float2half_rn(w2[j]);
    for (int j = i; j < 256 * 768; j += stride) g_Wfh[j] = __float2half_rn(wf[j]);
}

__global__ void __launch_bounds__(256, 2)
l1_kernel(const float* __restrict__ update, const float* __restrict__ b1_0,
          const float* __restrict__ b1, int nrows) {
    int g = blockIdx.y;
    if (g == 0) {
        gemm_l1<1280>(update, 4352, 0, 0, 1 << 20,
                      g_W1_0h, 1280, b1_0, g_out1h, 896, nrows);
    } else {
        gemm_l1<512>(update, 4352, c_jA[g] * 256, c_jB[g] * 256, 256,
                     g_W1h + (g - 1) * 128 * 512, 512, b1 + (g - 1) * 128,
                     g_out1h + g * 128, 896, nrows);
    }
}

__global__ void __launch_bounds__(256, 2)
l2_kernel(const float* __restrict__ b2, int nrows) {
    int g = blockIdx.y;
    gemm_pp<true, 256>(g_out1h, 896, c_pA[g] * 128, c_pB[g] * 128, 128,
                       g_W2h + g * 128 * 256, 256, b2 + g * 128,
                       g_out2h + g * 128, 768, nrows);
}

__global__ void __launch_bounds__(256, 2)
l3_kernel(const float* __restrict__ bf, float* __restrict__ out, int nrows) {
    int y = blockIdx.y;   // output column half
    gemm_pp<false, 768>(g_out2h, 768, 0, 0, 1 << 20,
                        g_Wfh + y * 128 * 768, 768, bf + y * 128,
                        out + y * 128, 256, nrows);
}

// ---------------- launch ----------------

extern "C" void kernel_launch(void* const* d_in, const int* in_sizes, int n_in,
                              void* d_out, int out_size) {
    const float* update = (const float*)d_in[0];
    const float* W1_0   = (const float*)d_in[1];
    const float* b1_0   = (const float*)d_in[2];
    const float* W1     = (const float*)d_in[3];
    const float* b1     = (const float*)d_in[4];
    const float* W2     = (const float*)d_in[5];
    const float* b2     = (const float*)d_in[6];
    const float* Wf     = (const float*)d_in[7];
    const float* bf     = (const float*)d_in[8];

    int N   = in_sizes[0] / (17 * 256);
    int MT1 = (N + 127) / 128;
    int MT2 = (N + 63) / 64;

    cudaFuncSetAttribute(l1_kernel, cudaFuncAttributeMaxDynamicSharedMemorySize, SMEM_L1);
    cudaFuncSetAttribute(l2_kernel, cudaFuncAttributeMaxDynamicSharedMemorySize, SMEM_PP);
    cudaFuncSetAttribute(l3_kernel, cudaFuncAttributeMaxDynamicSharedMemorySize, SMEM_PP);

    prep_kernel<<<232, 256>>>(W1_0, W1, W2, Wf);
    l1_kernel<<<dim3(MT1, 7), 256, SMEM_L1>>>(update, b1_0, b1, N);
    l2_kernel<<<dim3(MT2, 6), 256, SMEM_PP>>>(b2, N);
    l3_kernel<<<dim3(MT2, 2), 256, SMEM_PP>>>(bf, (float*)d_out, N);
}

// round 14
// speedup vs baseline: 1.0104x; 1.0104x over previous
#include <cuda_runtime.h>
#include <cuda_fp16.h>
#include <cstdint>

// ---------------------------------------------------------------------------
// HierarchUpdateMlp — fp16 mma.sync (m16n8k16), K-stage 64.
//   L1/L2: R7-exact pipelines (best known: 379.1us).
//   L3: 64x256 block tile (full output width) — halves A (out2) re-reads.
//       R13 bug fixed: A fill source now includes the per-thread fj*8 column.
// fp16 smem tiles: rows x 64 halfs (128B rows), chunk pos = j ^ (row&7).
// ---------------------------------------------------------------------------

#define NROWS_MAX 50176   // N = 50000

__device__ __align__(16) __half g_W1_0h[128 * 1280];
__device__ __align__(16) __half g_W1h[6 * 128 * 512];
__device__ __align__(16) __half g_W2h[6 * 128 * 256];
__device__ __align__(16) __half g_Wfh[256 * 768];
__device__ __align__(16) __half g_out1h[(size_t)NROWS_MAX * 896];
__device__ __align__(16) __half g_out2h[(size_t)NROWS_MAX * 768];

__constant__ int c_jA[7] = {0, 5, 7, 8, 11, 13, 14};
__constant__ int c_jB[7] = {0, 6, 9, 10, 12, 15, 16};
__constant__ int c_pA[6] = {0, 1, 1, 1, 4, 4};
__constant__ int c_pB[6] = {1, 2, 3, 4, 5, 6};

// smem (bytes):
//  L1 (MODE1): [0,32768) fp32 staging, [32768,49152) hA, [49152,81920) hB x2
//  L2 (MODE0): [0,32768) hA x2, [32768,65536) hB x2
//  L3 wide:    [0,16384) hA x2 (64x64), [16384,81920) hB x2 (256x64)
#define SMEM_L1 81920
#define SMEM_L2 65536
#define SMEM_L3 81920

__device__ __forceinline__ unsigned smem_u32(const void* p) {
    return (unsigned)__cvta_generic_to_shared(p);
}

__device__ __forceinline__ void ldsm4(unsigned addr, unsigned& r0, unsigned& r1,
                                      unsigned& r2, unsigned& r3) {
    asm volatile("ldmatrix.sync.aligned.m8n8.x4.shared.b16 {%0,%1,%2,%3}, [%4];"
                 : "=r"(r0), "=r"(r1), "=r"(r2), "=r"(r3)
                 : "r"(addr));
}

__device__ __forceinline__ void mma_f16(float* c, const unsigned* a, const unsigned* b) {
    asm volatile(
        "mma.sync.aligned.m16n8k16.row.col.f32.f16.f16.f32 "
        "{%0,%1,%2,%3}, {%4,%5,%6,%7}, {%8,%9}, {%0,%1,%2,%3};"
        : "+f"(c[0]), "+f"(c[1]), "+f"(c[2]), "+f"(c[3])
        : "r"(a[0]), "r"(a[1]), "r"(a[2]), "r"(a[3]), "r"(b[0]), "r"(b[1]));
}

// ==================== L1/L2 generic GEMM (R7-exact) =========================
template <int MODE, bool HALF_OUT, int K>
__device__ __forceinline__ void gemm16(
    const void* __restrict__ Av, int lda, int offA0, int offA1, int blk,
    const __half* __restrict__ B, int ldb,
    const float* __restrict__ bias,
    void* __restrict__ Cv, int ldc,
    int nrows)
{
    extern __shared__ char smc[];
    float*  stg = reinterpret_cast<float*>(smc);                       // MODE1 only
    __half* hA  = reinterpret_cast<__half*>(smc + (MODE ? 32768 : 0));
    __half* hB  = hA + (MODE ? 8192 : 16384);

    const int tid   = threadIdx.x;
    const int lane  = tid & 31;
    const int wid   = tid >> 5;
    const int warpM = wid & 3;
    const int warpN = wid >> 2;
    const int tile  = blockIdx.x * 128;
    constexpr int KT = K >> 6;

    float acc[2][8][4];
#pragma unroll
    for (int i = 0; i < 2; i++)
#pragma unroll
        for (int j = 0; j < 8; j++)
#pragma unroll
            for (int q = 0; q < 4; q++) acc[i][j][q] = 0.f;

    const int rowIn = (lane & 7) + ((lane >> 3) & 1) * 8;
    const int hi    = (lane >> 4) & 1;

    const int fr8  = tid >> 3;
    const int fj   = tid & 7;
    const int fr16 = tid >> 4;
    const int fj16 = tid & 15;

    const __half* bSrc0 = B + (long)fr8 * ldb + fj * 8;
    unsigned bDst[4];
#pragma unroll
    for (int i = 0; i < 4; ++i) {
        int r = fr8 + i * 32;
        bDst[i] = smem_u32(hB + r * 64 + 8 * (fj ^ (r & 7)));
    }
    auto fillB = [&](int kt) {
        const unsigned boff = (unsigned)((kt & 1) * 16384);
        const __half* src = bSrc0 + (kt << 6);
#pragma unroll
        for (int i = 0; i < 4; ++i)
            asm volatile("cp.async.cg.shared.global [%0], [%1], 16;"
                         ::"r"(bDst[i] + boff), "l"(src + (long)i * 32 * ldb));
    };

    const __half* a0Src[4];
    unsigned a0Dst[4];
    if (MODE == 0) {
#pragma unroll
        for (int i = 0; i < 4; ++i) {
            int r = fr8 + i * 32;
            int row = tile + r; if (row >= nrows) row = nrows - 1;
            a0Src[i] = (const __half*)Av + (long)row * lda;
            a0Dst[i] = smem_u32(hA + r * 64 + 8 * (fj ^ (r & 7)));
        }
    }
    auto fillA0 = [&](int kt) {
        const unsigned boff = (unsigned)((kt & 1) * 16384);
        int k   = (kt << 6) + fj * 8;
        int col = (k < blk) ? (offA0 + k) : (offA1 + (k - blk));
#pragma unroll
        for (int i = 0; i < 4; ++i)
            asm volatile("cp.async.cg.shared.global [%0], [%1], 16;"
                         ::"r"(a0Dst[i] + boff), "l"(a0Src[i] + col));
    };

    const float* a1Src[8];
    unsigned a1Dst[8];
    if (MODE == 1) {
#pragma unroll
        for (int i = 0; i < 8; ++i) {
            int r = fr16 + i * 16;
            int row = tile + r; if (row >= nrows) row = nrows - 1;
            a1Src[i] = (const float*)Av + (long)row * lda;
            a1Dst[i] = smem_u32(stg + r * 64 +
                                4 * ((fj16 & 8) | ((fj16 & 7) ^ (r & 7))));
        }
    }
    auto fillA1 = [&](int kt) {
        int k   = (kt << 6) + fj16 * 4;
        int col = (k < blk) ? (offA0 + k) : (offA1 + (k - blk));
#pragma unroll
        for (int i = 0; i < 8; ++i)
            asm volatile("cp.async.cg.shared.global [%0], [%1], 16;"
                         ::"r"(a1Dst[i]), "l"(a1Src[i] + col));
    };

    auto convertA = [&]() {
        const int r  = tid >> 1;
        const int h  = tid & 1;
        const int rx = r & 7;
#pragma unroll
        for (int q = 0; q < 4; ++q) {
            float4 va = *reinterpret_cast<const float4*>(
                stg + r * 64 + 4 * (h * 8 + ((2 * q) ^ rx)));
            float4 vb = *reinterpret_cast<const float4*>(
                stg + r * 64 + 4 * (h * 8 + ((2 * q + 1) ^ rx)));
            __half2 h0 = __floats2half2_rn(va.x, va.y);
            __half2 h1 = __floats2half2_rn(va.z, va.w);
            __half2 h2 = __floats2half2_rn(vb.x, vb.y);
            __half2 h3 = __floats2half2_rn(vb.z, vb.w);
            uint4 u;
            u.x = *reinterpret_cast<unsigned*>(&h0);
            u.y = *reinterpret_cast<unsigned*>(&h1);
            u.z = *reinterpret_cast<unsigned*>(&h2);
            u.w = *reinterpret_cast<unsigned*>(&h3);
            *reinterpret_cast<uint4*>(hA + r * 64 + 8 * ((h * 4 + q) ^ rx)) = u;
        }
    };

    auto compute_stage = [&](int buf) {
        const __half* As = hA + (MODE ? 0 : buf * 8192);
        const __half* Bs = hB + buf * 8192;
#pragma unroll
        for (int s = 0; s < 4; ++s) {
            const int j = 2 * s + hi;
            unsigned a[2][4];
#pragma unroll
            for (int mf = 0; mf < 2; ++mf) {
                int row = warpM * 32 + mf * 16 + rowIn;
                ldsm4(smem_u32(As + row * 64 + 8 * (j ^ (row & 7))),
                      a[mf][0], a[mf][1], a[mf][2], a[mf][3]);
            }
            unsigned b[8][2];
#pragma unroll
            for (int nq = 0; nq < 4; ++nq) {
                int nrow = warpN * 64 + nq * 16 + rowIn;
                unsigned r0, r1, r2, r3;
                ldsm4(smem_u32(Bs + nrow * 64 + 8 * (j ^ (nrow & 7))),
                      r0, r1, r2, r3);
                b[nq * 2][0]     = r0;
                b[nq * 2 + 1][0] = r1;
                b[nq * 2][1]     = r2;
                b[nq * 2 + 1][1] = r3;
            }
#pragma unroll
            for (int mf = 0; mf < 2; ++mf)
#pragma unroll
                for (int nf = 0; nf < 8; ++nf)
                    mma_f16(acc[mf][nf], a[mf], b[nf]);
        }
    };

    if (MODE == 1) {
        fillA1(0); fillB(0);
        asm volatile("cp.async.commit_group;");
#pragma unroll 4
        for (int kt = 0; kt < KT; ++kt) {
            asm volatile("cp.async.wait_group 0;" ::: "memory");
            __syncthreads();
            convertA();
            __syncthreads();
            if (kt + 1 < KT) {
                fillA1(kt + 1); fillB(kt + 1);
                asm volatile("cp.async.commit_group;");
            }
            compute_stage(kt & 1);
        }
    } else {
        fillA0(0); fillB(0);
        asm volatile("cp.async.commit_group;");
#pragma unroll 4
        for (int kt = 0; kt < KT; ++kt) {
            if (kt + 1 < KT) {
                fillA0(kt + 1); fillB(kt + 1);
                asm volatile("cp.async.commit_group;");
                asm volatile("cp.async.wait_group 1;" ::: "memory");
            } else {
                asm volatile("cp.async.wait_group 0;" ::: "memory");
            }
            __syncthreads();
            compute_stage(kt & 1);
            __syncthreads();
        }
    }

    const int rbase = tile + warpM * 32 + (lane >> 2);
#pragma unroll
    for (int mf = 0; mf < 2; ++mf) {
        int r0 = rbase + mf * 16;
#pragma unroll
        for (int nf = 0; nf < 8; ++nf) {
            int col  = warpN * 64 + nf * 8 + (lane & 3) * 2;
            float b0 = __ldg(bias + col);
            float b1 = __ldg(bias + col + 1);
            float v0 = fmaxf(acc[mf][nf][0] + b0, 0.f);
            float v1 = fmaxf(acc[mf][nf][1] + b1, 0.f);
            float v2 = fmaxf(acc[mf][nf][2] + b0, 0.f);
            float v3 = fmaxf(acc[mf][nf][3] + b1, 0.f);
            if (HALF_OUT) {
                __half* Ch = (__half*)Cv;
                if (r0 < nrows)
                    *reinterpret_cast<__half2*>(Ch + (long)r0 * ldc + col) =
                        __floats2half2_rn(v0, v1);
                if (r0 + 8 < nrows)
                    *reinterpret_cast<__half2*>(Ch + (long)(r0 + 8) * ldc + col) =
                        __floats2half2_rn(v2, v3);
            } else {
                float* Cf = (float*)Cv;
                if (r0 < nrows)
                    *reinterpret_cast<float2*>(Cf + (long)r0 * ldc + col) =
                        make_float2(v0, v1);
                if (r0 + 8 < nrows)
                    *reinterpret_cast<float2*>(Cf + (long)(r0 + 8) * ldc + col) =
                        make_float2(v2, v3);
            }
        }
    }
}

// ==================== L3: 64(M) x 256(N) wide-tile GEMM =====================
// Warps: warpM = wid&1 (m32), warpN = wid>>1 (n64 of 256). K=768, 12 stages.
// A read ONCE per 64-row tile (was twice with the 2-way N split).
template <int K>
__device__ __forceinline__ void gemm_l3wide(
    const __half* __restrict__ A, int lda,
    const __half* __restrict__ B, int ldb,
    const float* __restrict__ bias,
    float* __restrict__ C, int ldc,
    int nrows)
{
    extern __shared__ char smc[];
    __half* hA = reinterpret_cast<__half*>(smc);            // 2 x 4096 halfs
    __half* hB = reinterpret_cast<__half*>(smc + 16384);    // 2 x 16384 halfs

    const int tid   = threadIdx.x;
    const int lane  = tid & 31;
    const int wid   = tid >> 5;
    const int warpM = wid & 1;      // 2 warps over M (32 rows)
    const int warpN = wid >> 1;     // 4 warps over N (64 cols each)
    const int tile  = blockIdx.x * 64;
    constexpr int KT = K >> 6;      // 12

    float acc[2][8][4];
#pragma unroll
    for (int i = 0; i < 2; i++)
#pragma unroll
        for (int j = 0; j < 8; j++)
#pragma unroll
            for (int q = 0; q < 4; q++) acc[i][j][q] = 0.f;

    const int rowIn = (lane & 7) + ((lane >> 3) & 1) * 8;
    const int hi    = (lane >> 4) & 1;

    // fill geometry: r = tid>>3 (0..31, stride 32 per i), j = tid&7
    const int fr = tid >> 3;
    const int fj = tid & 7;

    // FIX (R13 bug): include the per-thread column offset fj*8 in the A source.
    const __half* aSrc[2];
#pragma unroll
    for (int i = 0; i < 2; ++i) {
        int row = tile + fr + i * 32;
        if (row >= nrows) row = nrows - 1;
        aSrc[i] = A + (long)row * lda + fj * 8;
    }
    const unsigned aDst0 = smem_u32(hA + fr * 64 + 8 * (fj ^ (fr & 7)));
    const __half*  bSrc0 = B + (long)fr * ldb + fj * 8;
    const unsigned bDst0 = smem_u32(hB + fr * 64 + 8 * (fj ^ (fr & 7)));

    auto fill = [&](int kt) {
        const int kg = kt << 6;
        const unsigned ab = (unsigned)((kt & 1) * 8192) + aDst0;    // bytes
#pragma unroll
        for (int i = 0; i < 2; ++i)
            asm volatile("cp.async.cg.shared.global [%0], [%1], 16;"
                         ::"r"(ab + i * 4096u), "l"(aSrc[i] + kg));
        const unsigned bb = (unsigned)((kt & 1) * 32768) + bDst0;
        const __half* src = bSrc0 + kg;
#pragma unroll
        for (int i = 0; i < 8; ++i)
            asm volatile("cp.async.cg.shared.global [%0], [%1], 16;"
                         ::"r"(bb + i * 4096u), "l"(src + (long)i * 32 * ldb));
        asm volatile("cp.async.commit_group;");
    };

    auto compute_stage = [&](int buf) {
        const __half* As = hA + buf * 4096;
        const __half* Bs = hB + buf * 16384;
#pragma unroll
        for (int s = 0; s < 4; ++s) {
            const int j = 2 * s + hi;
            unsigned a[2][4];
#pragma unroll
            for (int mf = 0; mf < 2; ++mf) {
                int row = warpM * 32 + mf * 16 + rowIn;      // 0..63
                ldsm4(smem_u32(As + row * 64 + 8 * (j ^ (row & 7))),
                      a[mf][0], a[mf][1], a[mf][2], a[mf][3]);
            }
            unsigned b[8][2];
#pragma unroll
            for (int nq = 0; nq < 4; ++nq) {
                int nrow = warpN * 64 + nq * 16 + rowIn;     // 0..255
                unsigned r0, r1, r2, r3;
                ldsm4(smem_u32(Bs + nrow * 64 + 8 * (j ^ (nrow & 7))),
                      r0, r1, r2, r3);
                b[nq * 2][0]     = r0;
                b[nq * 2 + 1][0] = r1;
                b[nq * 2][1]     = r2;
                b[nq * 2 + 1][1] = r3;
            }
#pragma unroll
            for (int mf = 0; mf < 2; ++mf)
#pragma unroll
                for (int nf = 0; nf < 8; ++nf)
                    mma_f16(acc[mf][nf], a[mf], b[nf]);
        }
    };

    fill(0);
#pragma unroll 4
    for (int kt = 0; kt < KT; ++kt) {
        asm volatile("cp.async.wait_group 0;" ::: "memory");
        __syncthreads();            // fill(kt) visible; compute(kt-1) done
        if (kt + 1 < KT) fill(kt + 1);
        compute_stage(kt & 1);
    }

    const int rbase = tile + warpM * 32 + (lane >> 2);
#pragma unroll
    for (int mf = 0; mf < 2; ++mf) {
        int r0 = rbase + mf * 16;
#pragma unroll
        for (int nf = 0; nf < 8; ++nf) {
            int col  = warpN * 64 + nf * 8 + (lane & 3) * 2;
            float b0 = __ldg(bias + col);
            float b1 = __ldg(bias + col + 1);
            float v0 = fmaxf(acc[mf][nf][0] + b0, 0.f);
            float v1 = fmaxf(acc[mf][nf][1] + b1, 0.f);
            float v2 = fmaxf(acc[mf][nf][2] + b0, 0.f);
            float v3 = fmaxf(acc[mf][nf][3] + b1, 0.f);
            if (r0 < nrows)
                *reinterpret_cast<float2*>(C + (long)r0 * ldc + col) =
                    make_float2(v0, v1);
            if (r0 + 8 < nrows)
                *reinterpret_cast<float2*>(C + (long)(r0 + 8) * ldc + col) =
                    make_float2(v2, v3);
        }
    }
}

// ---------------- kernels ----------------

__global__ void prep_kernel(const float* __restrict__ w10, const float* __restrict__ w1,
                            const float* __restrict__ w2, const float* __restrict__ wf) {
    int i      = blockIdx.x * blockDim.x + threadIdx.x;
    int stride = gridDim.x * blockDim.x;
    for (int j = i; j < 128 * 1280; j += stride) g_W1_0h[j] = __float2half_rn(w10[j]);
    for (int j = i; j < 6 * 128 * 512; j += stride) g_W1h[j] = __float2half_rn(w1[j]);
    for (int j = i; j < 6 * 128 * 256; j += stride) g_W2h[j] = __float2half_rn(w2[j]);
    for (int j = i; j < 256 * 768; j += stride) g_Wfh[j] = __float2half_rn(wf[j]);
}

__global__ void __launch_bounds__(256, 2)
l1_kernel(const float* __restrict__ update, const float* __restrict__ b1_0,
          const float* __restrict__ b1, int nrows) {
    int g = blockIdx.y;
    if (g == 0) {
        gemm16<1, true, 1280>(update, 4352, 0, 0, 1 << 20,
                              g_W1_0h, 1280, b1_0, g_out1h, 896, nrows);
    } else {
        gemm16<1, true, 512>(update, 4352, c_jA[g] * 256, c_jB[g] * 256, 256,
                             g_W1h + (g - 1) * 128 * 512, 512, b1 + (g - 1) * 128,
                             g_out1h + g * 128, 896, nrows);
    }
}

__global__ void __launch_bounds__(256, 2)
l2_kernel(const float* __restrict__ b2, int nrows) {
    int g = blockIdx.y;
    gemm16<0, true, 256>(g_out1h, 896, c_pA[g] * 128, c_pB[g] * 128, 128,
                         g_W2h + g * 128 * 256, 256, b2 + g * 128,
                         g_out2h + g * 128, 768, nrows);
}

__global__ void __launch_bounds__(256, 2)
l3_kernel(const float* __restrict__ bf, float* __restrict__ out, int nrows) {
    gemm_l3wide<768>(g_out2h, 768, g_Wfh, 768, bf, out, 256, nrows);
}

// ---------------- launch ----------------

extern "C" void kernel_launch(void* const* d_in, const int* in_sizes, int n_in,
                              void* d_out, int out_size) {
    const float* update = (const float*)d_in[0];
    const float* W1_0   = (const float*)d_in[1];
    const float* b1_0   = (const float*)d_in[2];
    const float* W1     = (const float*)d_in[3];
    const float* b1     = (const float*)d_in[4];
    const float* W2     = (const float*)d_in[5];
    const float* b2     = (const float*)d_in[6];
    const float* Wf     = (const float*)d_in[7];
    const float* bf     = (const float*)d_in[8];

    int N    = in_sizes[0] / (17 * 256);
    int MT1  = (N + 127) / 128;
    int MT64 = (N + 63) / 64;

    cudaFuncSetAttribute(l1_kernel, cudaFuncAttributeMaxDynamicSharedMemorySize, SMEM_L1);
    cudaFuncSetAttribute(l2_kernel, cudaFuncAttributeMaxDynamicSharedMemorySize, SMEM_L2);
    cudaFuncSetAttribute(l3_kernel, cudaFuncAttributeMaxDynamicSharedMemorySize, SMEM_L3);

    prep_kernel<<<232, 256>>>(W1_0, W1, W2, Wf);
    l1_kernel<<<dim3(MT1, 7), 256, SMEM_L1>>>(update, b1_0, b1, N);
    l2_kernel<<<dim3(MT1, 6), 256, SMEM_L2>>>(b2, N);
    l3_kernel<<<MT64, 256, SMEM_L3>>>(bf, (float*)d_out, N);
}